// round 15
// baseline (speedup 1.0000x reference)
#include <cuda_runtime.h>
#include <cuda_bf16.h>
#include <stdint.h>
#include <math.h>

#define NP 3136
#define Bb 2
#define CN 802816L
#define C2N 1605632L
#define TOT 1605632L
#define HT 1792
#define NPH 1568
#define T3N (29*56)

// ---------------- scratch ----------------
static __device__ float g_sq  [TOT];
static __device__ float g_skv [Bb*C2N];
static __device__ float g_tq  [TOT];
static __device__ float g_tkv [Bb*C2N];
static __device__ float g_spre[TOT];
static __device__ float g_xat [TOT];
static __device__ float g_fusb[Bb*C2N];
static __device__ float g_hbuf[TOT];
static __device__ float g_gate[Bb*NP];
static __device__ float g_osp [2*TOT];          // split-K unnormalized O
static __device__ float g_mv  [2*16*NP];        // split-K row max
static __device__ float g_lv  [2*16*NP];        // split-K row sum
static __device__ __nv_bfloat162 g_qb[Bb*8L*NP*16];
static __device__ __nv_bfloat162 g_kb[Bb*8L*NP*16];
static __device__ __nv_bfloat162 g_vb[Bb*256L*NPH];
static __device__ float2 gT1[HT];               // twiddle tables (shared, L1-resident)
static __device__ float2 gT2[NP];
static __device__ float2 gT3[T3N];

// ---------------- table init (1 block) ----------------
__global__ void init_tables_k()
{
    int tid = threadIdx.x;
    for (int i = tid; i < HT; i += 256) {
        int n = i >> 5, k = i & 31;
        float c = 0.f, s = 0.f;
        if (k < 29) { int m = (n * k) % 56; sincospif(2.f * (float)m / 56.f, &s, &c); }
        gT1[i] = make_float2(c, s);
    }
    for (int i = tid; i < NP; i += 256) {
        int r = i / 56, kh = i % 56;
        int m = (r * kh) % 56;
        float c, s; sincospif(2.f * (float)m / 56.f, &s, &c);
        gT2[i] = make_float2(c, s);
    }
    for (int i = tid; i < T3N; i += 256) {
        int k = i / 56, x = i % 56;
        int m = (k * x) % 56;
        float c, s; sincospif(2.f * (float)m / 56.f, &s, &c);
        float mult = (k == 0 || k == 28) ? 1.f : 2.f;
        gT3[i] = make_float2(mult * c, -mult * s);
    }
}

// ---------------- TF32 GEMM core ----------------
__device__ __forceinline__ float tf32r(float x)
{
    uint32_t u;
    asm("cvt.rna.tf32.f32 %0, %1;" : "=r"(u) : "f"(x));
    return __uint_as_float(u);
}

__device__ __forceinline__ void mma_tf32(float* c, const uint32_t* a, const uint32_t* b)
{
    asm volatile("mma.sync.aligned.m16n8k8.row.col.f32.tf32.tf32.f32 "
                 "{%0,%1,%2,%3}, {%4,%5,%6,%7}, {%8,%9}, {%0,%1,%2,%3};"
                 : "+f"(c[0]), "+f"(c[1]), "+f"(c[2]), "+f"(c[3])
                 : "r"(a[0]), "r"(a[1]), "r"(a[2]), "r"(a[3]), "r"(b[0]), "r"(b[1]));
}

__device__ __forceinline__ void gemm_core(const float* __restrict__ W,
                                          const float* __restrict__ X,
                                          float* __restrict__ Y,
                                          const float* __restrict__ bias,
                                          int I, int nb,
                                          float (*Ws)[20], float (*Xs)[65])
{
    int tid = threadIdx.x;
    int warp = tid >> 5, lane = tid & 31;
    int g = lane >> 2, j = lane & 3;
    int warp_o = warp & 3, warp_n = warp >> 2;

    float acc[2][4][4];
#pragma unroll
    for (int mo = 0; mo < 2; mo++)
#pragma unroll
        for (int nn = 0; nn < 4; nn++)
#pragma unroll
            for (int r = 0; r < 4; r++) acc[mo][nn][r] = 0.f;

    int wrow = tid >> 1, whf = (tid & 1) * 8;
    int xrow = tid >> 4, xc4 = (tid & 15) * 4;

    for (int kt = 0; kt < I; kt += 16) {
        float4 w0 = *(const float4*)&W[(long)wrow * I + kt + whf];
        float4 w1 = *(const float4*)&W[(long)wrow * I + kt + whf + 4];
        Ws[wrow][whf + 0] = tf32r(w0.x); Ws[wrow][whf + 1] = tf32r(w0.y);
        Ws[wrow][whf + 2] = tf32r(w0.z); Ws[wrow][whf + 3] = tf32r(w0.w);
        Ws[wrow][whf + 4] = tf32r(w1.x); Ws[wrow][whf + 5] = tf32r(w1.y);
        Ws[wrow][whf + 6] = tf32r(w1.z); Ws[wrow][whf + 7] = tf32r(w1.w);
        float4 xv = *(const float4*)&X[(long)(kt + xrow) * NP + nb + xc4];
        Xs[xrow][xc4 + 0] = tf32r(xv.x); Xs[xrow][xc4 + 1] = tf32r(xv.y);
        Xs[xrow][xc4 + 2] = tf32r(xv.z); Xs[xrow][xc4 + 3] = tf32r(xv.w);
        __syncthreads();
#pragma unroll
        for (int kk = 0; kk < 16; kk += 8) {
            uint32_t a[2][4], b[4][2];
#pragma unroll
            for (int mo = 0; mo < 2; mo++) {
                int r0 = warp_o * 32 + mo * 16 + g;
                a[mo][0] = __float_as_uint(Ws[r0][kk + j]);
                a[mo][1] = __float_as_uint(Ws[r0 + 8][kk + j]);
                a[mo][2] = __float_as_uint(Ws[r0][kk + j + 4]);
                a[mo][3] = __float_as_uint(Ws[r0 + 8][kk + j + 4]);
            }
#pragma unroll
            for (int nn = 0; nn < 4; nn++) {
                int cc = warp_n * 32 + nn * 8 + g;
                b[nn][0] = __float_as_uint(Xs[kk + j][cc]);
                b[nn][1] = __float_as_uint(Xs[kk + j + 4][cc]);
            }
#pragma unroll
            for (int mo = 0; mo < 2; mo++)
#pragma unroll
                for (int nn = 0; nn < 4; nn++)
                    mma_tf32(acc[mo][nn], a[mo], b[nn]);
        }
        __syncthreads();
    }

#pragma unroll
    for (int mo = 0; mo < 2; mo++) {
        int r0 = warp_o * 32 + mo * 16 + g;
        float bs0 = bias ? bias[r0] : 0.f;
        float bs1 = bias ? bias[r0 + 8] : 0.f;
#pragma unroll
        for (int nn = 0; nn < 4; nn++) {
            int col = nb + warp_n * 32 + nn * 8 + j * 2;
            float2 v0 = make_float2(acc[mo][nn][0] + bs0, acc[mo][nn][1] + bs0);
            float2 v1 = make_float2(acc[mo][nn][2] + bs1, acc[mo][nn][3] + bs1);
            *(float2*)&Y[(long)r0 * NP + col] = v0;
            *(float2*)&Y[(long)(r0 + 8) * NP + col] = v1;
        }
    }
}

__global__ void gemm_dualW_k(const float* __restrict__ W1, const float* __restrict__ W2,
                             int osplit, const float* __restrict__ X, long xB,
                             float* __restrict__ Y1, float* __restrict__ Y2, long yB, int I)
{
    __shared__ float Ws[128][20];
    __shared__ float Xs[16][65];
    int ob = blockIdx.y * 128, b = blockIdx.z;
    const float* W; float* Y;
    if (ob < osplit) { W = W1 + (long)ob * I;            Y = Y1 + (long)b * yB + (long)ob * NP; }
    else             { W = W2 + (long)(ob - osplit) * I; Y = Y2 + (long)b * yB + (long)(ob - osplit) * NP; }
    gemm_core(W, X + (long)b * xB, Y, nullptr, I, blockIdx.x * 64, Ws, Xs);
}

__global__ void gemm_dualX_k(const float* __restrict__ W1, const float* __restrict__ W2,
                             const float* __restrict__ X1, const float* __restrict__ X2, long xB,
                             float* __restrict__ Y1, float* __restrict__ Y2, long yB,
                             const float* __restrict__ b1, const float* __restrict__ b2, int I)
{
    __shared__ float Ws[128][20];
    __shared__ float Xs[16][65];
    int z = blockIdx.z, b = z & 1, sel = z >> 1;
    int ob = blockIdx.y * 128;
    const float* W = (sel ? W2 : W1) + (long)ob * I;
    const float* X = (sel ? X2 : X1) + (long)b * xB;
    float*       Y = (sel ? Y2 : Y1) + (long)b * yB + (long)ob * NP;
    const float* bs = sel ? b2 : b1;
    gemm_core(W, X, Y, bs ? bs + ob : nullptr, I, blockIdx.x * 64, Ws, Xs);
}

__global__ void gemm_tf32_k(const float* __restrict__ W, const float* __restrict__ X,
                            float* __restrict__ Y, const float* __restrict__ bias,
                            int I, long xB, long yB)
{
    __shared__ float Ws[128][20];
    __shared__ float Xs[16][65];
    int ob = blockIdx.y * 128, b = blockIdx.z;
    gemm_core(W + (long)ob * I, X + (long)b * xB, Y + (long)b * yB + (long)ob * NP,
              bias ? bias + ob : nullptr, I, blockIdx.x * 64, Ws, Xs);
}

// ---------------- DFT stages (tables in global/L1) ----------------
__device__ __forceinline__ void r2cw_stage(const float* img, float2* out, int tid)
{
    for (int o = tid; o < HT; o += 256) {
        int r = o >> 5, k = o & 31;
        if (k >= 29) continue;
        const float* xr = img + r * 56;
        float ac = 0.f, as = 0.f;
#pragma unroll 14
        for (int n = 0; n < 56; n++) {
            float2 w = gT1[n * 32 + k];
            float v = xr[n];
            ac = fmaf(v, w.x, ac);
            as = fmaf(v, w.y, as);
        }
        out[o] = make_float2(ac, -as);
    }
}

template<int SG>
__device__ __forceinline__ void c2ch_stage(const float2* in, float2* out, int tid)
{
    for (int o = tid; o < HT; o += 256) {
        int kh = o >> 5, kx = o & 31;
        if (kx >= 29) continue;
        float pr = 0.f, pi = 0.f;
#pragma unroll 14
        for (int r = 0; r < 56; r++) {
            float2 w = gT2[r * 56 + kh];
            float2 v = in[r * 32 + kx];
            if (SG > 0) {
                pr = fmaf(v.x, w.x, fmaf(v.y, w.y, pr));
                pi = fmaf(v.y, w.x, fmaf(-v.x, w.y, pi));
            } else {
                pr = fmaf(v.x, w.x, fmaf(-v.y, w.y, pr));
                pi = fmaf(v.y, w.x, fmaf(v.x, w.y, pi));
            }
        }
        out[o] = make_float2(pr, pi);
    }
}

// ---------------- fused spectral branch ----------------
extern "C" __global__ void spec_fused_k(const float* __restrict__ sq,
                                        const float* __restrict__ skv,
                                        const float* __restrict__ dww,
                                        const float* __restrict__ dwb,
                                        float* __restrict__ out)
{
    extern __shared__ float sm[];
    float*  img = sm;
    float2* A   = (float2*)(sm + NP);
    float2* Bf  = A + HT;
    float2* Cf  = Bf + HT;
    int tid = threadIdx.x;
    int c = blockIdx.x, b = blockIdx.y;

    const float* qp = sq  + ((long)b * 256 + c) * NP;
    const float* kp = skv + ((long)b * 512 + c) * NP;
    const float* vp = skv + ((long)b * 512 + 256 + c) * NP;

    for (int i = tid; i < NP; i += 256) img[i] = qp[i];
    __syncthreads();
    r2cw_stage(img, A, tid);
    __syncthreads();
    c2ch_stage<1>(A, Cf, tid);
    for (int i = tid; i < NP; i += 256) img[i] = kp[i];
    __syncthreads();
    r2cw_stage(img, A, tid);
    __syncthreads();
    c2ch_stage<1>(A, Bf, tid);
    __syncthreads();
    for (int o = tid; o < HT; o += 256) {
        if ((o & 31) >= 29) continue;
        float2 a = Cf[o], bb = Bf[o];
        A[o] = make_float2(a.x * bb.x - a.y * bb.y, a.x * bb.y + a.y * bb.x);
    }
    __syncthreads();
    c2ch_stage<-1>(A, Bf, tid);
    for (int i = tid; i < NP; i += 256) img[i] = vp[i];
    __syncthreads();

    float wr[9];
#pragma unroll
    for (int i = 0; i < 9; i++) wr[i] = dww[c * 9 + i];
    float bsv = dwb[c];
    long ob = ((long)b * 256 + c) * NP;
    const float sc = 1.0f / 175616.0f;
    for (int o = tid; o < NP; o += 256) {
        int y = o / 56, x = o % 56;
        float acc = 0.f;
#pragma unroll
        for (int k = 0; k < 29; k++) {
            float2 w = gT3[k * 56 + x];
            float2 v = Bf[y * 32 + k];
            acc = fmaf(v.x, w.x, fmaf(v.y, w.y, acc));
        }
        float dv = bsv;
#pragma unroll
        for (int dy = -1; dy <= 1; dy++) {
            int yy = y + dy;
            if ((unsigned)yy >= 56u) continue;
#pragma unroll
            for (int dx = -1; dx <= 1; dx++) {
                int xx = x + dx;
                if ((unsigned)xx >= 56u) continue;
                dv += wr[(dy + 1) * 3 + dx + 1] * img[yy * 56 + xx];
            }
        }
        out[ob + o] = (sc * acc) * img[o] + dv;
    }
}

// ---------------- fused token spectral-residual ----------------
extern "C" __global__ void token_fused_k(const float* __restrict__ tkv,
                                         const float* __restrict__ cw,
                                         float* __restrict__ xat)
{
    extern __shared__ float sm[];
    float*  img = sm;
    float2* A   = (float2*)(sm + NP);
    float2* Bf  = A + HT;
    int tid = threadIdx.x;
    int c = blockIdx.x, b = blockIdx.y;

    const float* vp = tkv + (long)b * C2N + CN + (long)c * NP;
    for (int i = tid; i < NP; i += 256) img[i] = vp[i];
    __syncthreads();
    r2cw_stage(img, A, tid);
    __syncthreads();
    c2ch_stage<1>(A, Bf, tid);
    __syncthreads();
    for (int o = tid; o < HT; o += 256) {
        int kx = o & 31;
        if (kx >= 29) continue;
        int ky = o >> 5;
        long wb = (((long)c * 56 + ky) * 29 + kx) * 2;
        float wrr = cw[wb], wii = cw[wb + 1];
        float2 v = Bf[o];
        Bf[o] = make_float2(v.x * wrr - v.y * wii, v.x * wii + v.y * wrr);
    }
    __syncthreads();
    c2ch_stage<-1>(Bf, A, tid);
    __syncthreads();
    long ob = ((long)b * 256 + c) * NP;
    const float sc = 1.0f / 3136.0f;
    for (int o = tid; o < NP; o += 256) {
        int y = o / 56, x = o % 56;
        float acc = 0.f;
#pragma unroll
        for (int k = 0; k < 29; k++) {
            float2 w = gT3[k * 56 + x];
            float2 v = A[y * 32 + k];
            acc = fmaf(v.x, w.x, fmaf(v.y, w.y, acc));
        }
        xat[ob + o] += sc * acc;
    }
}

// ---------------- bf16 conversions ----------------
__global__ void cvtqk2_k(const float* __restrict__ tq, const float* __restrict__ tkv,
                         __nv_bfloat162* __restrict__ qb, __nv_bfloat162* __restrict__ kb,
                         float scale)
{
    const long HALF = (long)Bb * 8 * NP * 16;
    long i = (long)blockIdx.x * blockDim.x + threadIdx.x;
    if (i >= 2 * HALF) return;
    int isK = i >= HALF;
    long ii = isK ? i - HALF : i;
    int p = (int)(ii & 15);
    long t = ii >> 4;
    int n = (int)(t % NP);
    long t2 = t / NP;
    int h = (int)(t2 & 7), b = (int)(t2 >> 3);
    if (isK) {
        long s0 = (long)b * C2N + (long)(h * 32 + 2 * p) * NP + n;
        kb[ii] = __floats2bfloat162_rn(tkv[s0], tkv[s0 + NP]);
    } else {
        long s0 = (long)b * CN + (long)(h * 32 + 2 * p) * NP + n;
        qb[ii] = __floats2bfloat162_rn(tq[s0] * scale, tq[s0 + NP] * scale);
    }
}

__global__ void cvtv_k(const float* __restrict__ tkv, __nv_bfloat162* __restrict__ dst)
{
    long i = (long)blockIdx.x * blockDim.x + threadIdx.x;
    if (i >= (long)Bb * 256 * NPH) return;
    int n2 = (int)(i % NPH);
    long cr = i / NPH;
    int b = (int)(cr >> 8), c = (int)(cr & 255);
    long s = (long)b * C2N + CN + (long)c * NP + 2 * n2;
    dst[i] = __floats2bfloat162_rn(tkv[s], tkv[s + 1]);
}

// ---------------- split-K flash attention ----------------
__device__ __forceinline__ void mma16816(float* c, const uint32_t* a, const uint32_t* b)
{
    asm volatile("mma.sync.aligned.m16n8k16.row.col.f32.bf16.bf16.f32 "
                 "{%0,%1,%2,%3}, {%4,%5,%6,%7}, {%8,%9}, {%0,%1,%2,%3};"
                 : "+f"(c[0]), "+f"(c[1]), "+f"(c[2]), "+f"(c[3])
                 : "r"(a[0]), "r"(a[1]), "r"(a[2]), "r"(a[3]), "r"(b[0]), "r"(b[1]));
}

__device__ __forceinline__ uint32_t packbf(float lo, float hi)
{
    __nv_bfloat162 h = __floats2bfloat162_rn(lo, hi);
    return *(uint32_t*)&h;
}

// grid(25, 8, Bb*2): z = b + 2*split. 49 key-tiles per split.
__global__ void flash_mma_k(const __nv_bfloat162* __restrict__ Qb,
                            const __nv_bfloat162* __restrict__ Kb,
                            const __nv_bfloat162* __restrict__ Vb,
                            float* __restrict__ Osp, float* __restrict__ Mv,
                            float* __restrict__ Lv)
{
    __shared__ uint32_t Ks[32 * 16];
    __shared__ uint32_t Vs[32 * 16];
    int z = blockIdx.z, b = z & 1, split = z >> 1;
    int h = blockIdx.y;
    int tid = threadIdx.x;
    int warp = tid >> 5, lane = tid & 31;
    int g = lane >> 2, j = lane & 3;
    int q0 = blockIdx.x * 128 + warp * 16;
    bool act = q0 < NP;
    int q0c = act ? q0 : NP - 16;
    const uint32_t* Qh = (const uint32_t*)(Qb + (long)(b * 8 + h) * NP * 16);
    const uint32_t* Kh = (const uint32_t*)(Kb + (long)(b * 8 + h) * NP * 16);
    const uint32_t* Vh = (const uint32_t*)(Vb + (long)(b * 256 + h * 32) * NPH);

    uint32_t qa[2][4];
#pragma unroll
    for (int kc = 0; kc < 2; kc++) {
        qa[kc][0] = Qh[(q0c + g)     * 16 + kc * 8 + j];
        qa[kc][1] = Qh[(q0c + g + 8) * 16 + kc * 8 + j];
        qa[kc][2] = Qh[(q0c + g)     * 16 + kc * 8 + j + 4];
        qa[kc][3] = Qh[(q0c + g + 8) * 16 + kc * 8 + j + 4];
    }

    float o_[4][4];
#pragma unroll
    for (int d = 0; d < 4; d++)
#pragma unroll
        for (int r = 0; r < 4; r++) o_[d][r] = 0.f;
    float mlo = -1e30f, mhi = -1e30f, llo = 0.f, lhi = 0.f;

    int kt0 = split * 49;
#pragma unroll 1
    for (int kt = kt0; kt < kt0 + 49; kt++) {
        int kb = kt * 32;
        __syncthreads();
        {
            int t0 = tid, t1 = tid + 256;
            Ks[t0] = Kh[kb * 16 + t0];
            Ks[t1] = Kh[kb * 16 + t1];
            Vs[t0] = Vh[(long)(t0 >> 4) * NPH + (kb >> 1) + (t0 & 15)];
            Vs[t1] = Vh[(long)(t1 >> 4) * NPH + (kb >> 1) + (t1 & 15)];
        }
        __syncthreads();

        float s[2][2][4];
#pragma unroll
        for (int sub = 0; sub < 2; sub++) {
#pragma unroll
            for (int nc = 0; nc < 2; nc++) {
                uint32_t kf[2][2];
#pragma unroll
                for (int kc = 0; kc < 2; kc++) {
                    int keyl = sub * 16 + nc * 8 + g;
                    kf[kc][0] = Ks[keyl * 16 + kc * 8 + j];
                    kf[kc][1] = Ks[keyl * 16 + kc * 8 + j + 4];
                }
                s[sub][nc][0] = 0.f; s[sub][nc][1] = 0.f;
                s[sub][nc][2] = 0.f; s[sub][nc][3] = 0.f;
                mma16816(s[sub][nc], qa[0], kf[0]);
                mma16816(s[sub][nc], qa[1], kf[1]);
            }
        }

        float tlo = -1e30f, thi = -1e30f;
#pragma unroll
        for (int sub = 0; sub < 2; sub++)
#pragma unroll
            for (int nc = 0; nc < 2; nc++) {
                tlo = fmaxf(tlo, fmaxf(s[sub][nc][0], s[sub][nc][1]));
                thi = fmaxf(thi, fmaxf(s[sub][nc][2], s[sub][nc][3]));
            }
        tlo = fmaxf(tlo, __shfl_xor_sync(0xffffffff, tlo, 1));
        tlo = fmaxf(tlo, __shfl_xor_sync(0xffffffff, tlo, 2));
        thi = fmaxf(thi, __shfl_xor_sync(0xffffffff, thi, 1));
        thi = fmaxf(thi, __shfl_xor_sync(0xffffffff, thi, 2));
        float mnlo = fmaxf(mlo, tlo), mnhi = fmaxf(mhi, thi);
        float clo = __expf(mlo - mnlo), chi = __expf(mhi - mnhi);

        uint32_t pa[2][4];
        float sumlo = 0.f, sumhi = 0.f;
#pragma unroll
        for (int sub = 0; sub < 2; sub++) {
#pragma unroll
            for (int nc = 0; nc < 2; nc++) {
                float p0 = __expf(s[sub][nc][0] - mnlo);
                float p1 = __expf(s[sub][nc][1] - mnlo);
                float p2 = __expf(s[sub][nc][2] - mnhi);
                float p3 = __expf(s[sub][nc][3] - mnhi);
                sumlo += p0 + p1; sumhi += p2 + p3;
                pa[sub][nc * 2 + 0] = packbf(p0, p1);
                pa[sub][nc * 2 + 1] = packbf(p2, p3);
            }
        }
        sumlo += __shfl_xor_sync(0xffffffff, sumlo, 1);
        sumlo += __shfl_xor_sync(0xffffffff, sumlo, 2);
        sumhi += __shfl_xor_sync(0xffffffff, sumhi, 1);
        sumhi += __shfl_xor_sync(0xffffffff, sumhi, 2);
        llo = llo * clo + sumlo;
        lhi = lhi * chi + sumhi;
#pragma unroll
        for (int d = 0; d < 4; d++) {
            o_[d][0] *= clo; o_[d][1] *= clo;
            o_[d][2] *= chi; o_[d][3] *= chi;
        }
        mlo = mnlo; mhi = mnhi;

#pragma unroll
        for (int dc = 0; dc < 4; dc++) {
#pragma unroll
            for (int sub = 0; sub < 2; sub++) {
                uint32_t vf[2];
                int vrow = (dc * 8 + g) * 16 + sub * 8;
                vf[0] = Vs[vrow + j];
                vf[1] = Vs[vrow + j + 4];
                mma16816(o_[dc], pa[sub], vf);
            }
        }
    }

    if (act) {
        float* Ob = Osp + (long)split * TOT;
#pragma unroll
        for (int dc = 0; dc < 4; dc++) {
            long d0 = (long)(b * 256 + h * 32 + dc * 8 + 2 * j) * NP;
            Ob[d0 + q0 + g]          = o_[dc][0];
            Ob[d0 + NP + q0 + g]     = o_[dc][1];
            Ob[d0 + q0 + g + 8]      = o_[dc][2];
            Ob[d0 + NP + q0 + g + 8] = o_[dc][3];
        }
        if (j == 0) {
            long mb = ((long)split * 16 + b * 8 + h) * NP;
            Mv[mb + q0 + g] = mlo;     Lv[mb + q0 + g] = llo;
            Mv[mb + q0 + g + 8] = mhi; Lv[mb + q0 + g + 8] = lhi;
        }
    }
}

// combine split-K partials -> xat
__global__ void combine_k(const float* __restrict__ Osp, const float* __restrict__ Mv,
                          const float* __restrict__ Lv, float* __restrict__ xat)
{
    long i = (long)blockIdx.x * blockDim.x + threadIdx.x;
    if (i >= TOT) return;
    int row = (int)(i / NP);           // b*256 + h*32 + d
    int n = (int)(i % NP);
    int bh = row >> 5;                 // b*8 + h
    long mb = (long)bh * NP + n;
    float m0 = Mv[mb], m1 = Mv[16L * NP + mb];
    float l0 = Lv[mb], l1 = Lv[16L * NP + mb];
    float m = fmaxf(m0, m1);
    float a0 = __expf(m0 - m), a1 = __expf(m1 - m);
    float o = Osp[i] * a0 + Osp[TOT + i] * a1;
    xat[i] = o / (l0 * a0 + l1 * a1);
}

// ---------------- fuse ----------------
__global__ void gate_k(const float* __restrict__ hraw, const float* __restrict__ gam,
                       const float* __restrict__ bet, const float* __restrict__ w2,
                       const float* __restrict__ b2p, float* __restrict__ gate)
{
    int b = blockIdx.y;
    int n = blockIdx.x * 128 + threadIdx.x;
    if (n >= NP) return;
    const float inv = rsqrtf(1.f + 1e-5f);
    const float* hb = hraw + (long)b * CN + n;
    float g = b2p[0];
#pragma unroll 8
    for (int c = 0; c < 256; c++) {
        float hv = hb[(long)c * NP] * inv * gam[c] + bet[c];
        g = fmaf(w2[c], fmaxf(hv, 0.f), g);
    }
    gate[(long)b * NP + n] = 1.f / (1.f + __expf(-g));
}

__global__ void blend_k(const float* __restrict__ fuse, const float* __restrict__ gate,
                        float* __restrict__ out)
{
    long i = (long)blockIdx.x * blockDim.x + threadIdx.x;
    if (i >= TOT) return;
    long b = i / CN;
    long n = i % NP;
    float g = gate[b * NP + n];
    long fidx = i + b * CN;
    out[i] = g * fuse[fidx] + (1.f - g) * fuse[fidx + CN];
}

extern "C" void kernel_launch(void* const* d_in, const int* in_sizes, int n_in,
                              void* d_out, int out_size)
{
    const float* x        = (const float*)d_in[0];
    const float* ctx      = (const float*)d_in[1];
    const float* s_q_w    = (const float*)d_in[2];
    const float* s_kv_w   = (const float*)d_in[3];
    const float* s_proj_w = (const float*)d_in[4];
    const float* s_proj_b = (const float*)d_in[5];
    const float* s_dw_w   = (const float*)d_in[6];
    const float* s_dw_b   = (const float*)d_in[7];
    const float* t_q_w    = (const float*)d_in[8];
    const float* t_kv_w   = (const float*)d_in[9];
    const float* t_proj_w = (const float*)d_in[10];
    const float* t_proj_b = (const float*)d_in[11];
    const float* t_cw     = (const float*)d_in[12];
    const float* g_w1     = (const float*)d_in[13];
    const float* g_bn_g   = (const float*)d_in[14];
    const float* g_bn_b   = (const float*)d_in[15];
    const float* g_w2     = (const float*)d_in[16];
    const float* g_b2     = (const float*)d_in[17];
    float* out = (float*)d_out;

    float *sq, *skv, *tq, *tkv, *spre, *xat, *fuse, *hbuf, *gate, *osp, *mv, *lv;
    __nv_bfloat162 *qb, *kb, *vb;
    cudaGetSymbolAddress((void**)&sq,   g_sq);
    cudaGetSymbolAddress((void**)&skv,  g_skv);
    cudaGetSymbolAddress((void**)&tq,   g_tq);
    cudaGetSymbolAddress((void**)&tkv,  g_tkv);
    cudaGetSymbolAddress((void**)&spre, g_spre);
    cudaGetSymbolAddress((void**)&xat,  g_xat);
    cudaGetSymbolAddress((void**)&fuse, g_fusb);
    cudaGetSymbolAddress((void**)&hbuf, g_hbuf);
    cudaGetSymbolAddress((void**)&gate, g_gate);
    cudaGetSymbolAddress((void**)&osp,  g_osp);
    cudaGetSymbolAddress((void**)&mv,   g_mv);
    cudaGetSymbolAddress((void**)&lv,   g_lv);
    cudaGetSymbolAddress((void**)&qb,   g_qb);
    cudaGetSymbolAddress((void**)&kb,   g_kb);
    cudaGetSymbolAddress((void**)&vb,   g_vb);

    const int SPEC_SMEM  = (NP + 2 * 3 * HT) * 4;   // ~55.5 KB
    const int TOKEN_SMEM = (NP + 2 * 2 * HT) * 4;   // ~41 KB
    cudaFuncSetAttribute(spec_fused_k,  cudaFuncAttributeMaxDynamicSharedMemorySize, SPEC_SMEM);
    cudaFuncSetAttribute(token_fused_k, cudaFuncAttributeMaxDynamicSharedMemorySize, TOKEN_SMEM);

    const float SCALE = 0.17677669529663687f;
    dim3 blk256(256), blk128(128);
    dim3 gC(256, Bb);

    init_tables_k<<<1, 256>>>();

    gemm_dualW_k<<<dim3(49, 4, Bb), blk256>>>(s_q_w, t_q_w, 256, x, CN, sq, tq, CN, 256);
    gemm_dualW_k<<<dim3(49, 8, Bb), blk256>>>(s_kv_w, t_kv_w, 512, ctx, CN, skv, tkv, C2N, 256);

    spec_fused_k<<<gC, blk256, SPEC_SMEM>>>(sq, skv, s_dw_w, s_dw_b, spre);

    cvtqk2_k<<<dim3(6272), blk256>>>(tq, tkv, qb, kb, SCALE);
    cvtv_k<<<dim3(3136), blk256>>>(tkv, vb);
    flash_mma_k<<<dim3(25, 8, Bb * 2), blk256>>>(qb, kb, vb, osp, mv, lv);
    combine_k<<<dim3((unsigned)((TOT + 255) / 256)), blk256>>>(osp, mv, lv, xat);
    token_fused_k<<<gC, blk256, TOKEN_SMEM>>>(tkv, t_cw, xat);

    gemm_dualX_k<<<dim3(49, 2, 4), blk256>>>(s_proj_w, t_proj_w, spre, xat, CN,
                                             fuse, fuse + CN, C2N,
                                             s_proj_b, t_proj_b, 256);

    gemm_tf32_k<<<dim3(49, 2, Bb), blk256>>>(g_w1, fuse, hbuf, nullptr, 512, C2N, CN);
    gate_k<<<dim3(25, Bb), blk128>>>(hbuf, g_bn_g, g_bn_b, g_w2, g_b2, gate);
    blend_k<<<dim3((unsigned)((TOT + 255) / 256)), blk256>>>(fuse, gate, out);
}

// round 17
// speedup vs baseline: 1.0474x; 1.0474x over previous
#include <cuda_runtime.h>
#include <cuda_bf16.h>
#include <stdint.h>
#include <math.h>

#define NP 3136
#define Bb 2
#define CN 802816L
#define C2N 1605632L
#define TOT 1605632L
#define HT 1792
#define NPH 1568
#define T3N (29*56)

// ---------------- scratch ----------------
static __device__ float g_sq  [TOT];
static __device__ float g_skv [Bb*C2N];
static __device__ float g_tq  [TOT];
static __device__ float g_tkv [Bb*C2N];
static __device__ float g_spre[TOT];
static __device__ float g_xat [TOT];
static __device__ float g_fusb[Bb*C2N];
static __device__ float g_hbuf[TOT];
static __device__ float g_gate[Bb*NP];
static __device__ float g_osp [2*TOT];
static __device__ float g_mv  [2*16*NP];
static __device__ float g_lv  [2*16*NP];
static __device__ __nv_bfloat162 g_qb[Bb*8L*NP*16];
static __device__ __nv_bfloat162 g_kb[Bb*8L*NP*16];
static __device__ __nv_bfloat162 g_vb[Bb*256L*NPH];
static __device__ float2 gT1[HT];
static __device__ float2 gT2[NP];
static __device__ float2 gT3[T3N];

// ---------------- table init (1 block, once per call) ----------------
__global__ void init_tables_k()
{
    int tid = threadIdx.x;
    for (int i = tid; i < HT; i += 256) {
        int n = i >> 5, k = i & 31;
        float c = 0.f, s = 0.f;
        if (k < 29) { int m = (n * k) % 56; sincospif(2.f * (float)m / 56.f, &s, &c); }
        gT1[i] = make_float2(c, s);
    }
    for (int i = tid; i < NP; i += 256) {
        int r = i / 56, kh = i % 56;
        int m = (r * kh) % 56;
        float c, s; sincospif(2.f * (float)m / 56.f, &s, &c);
        gT2[i] = make_float2(c, s);
    }
    for (int i = tid; i < T3N; i += 256) {
        int k = i / 56, x = i % 56;
        int m = (k * x) % 56;
        float c, s; sincospif(2.f * (float)m / 56.f, &s, &c);
        float mult = (k == 0 || k == 28) ? 1.f : 2.f;
        gT3[i] = make_float2(mult * c, -mult * s);
    }
}

// ---------------- TF32 GEMM core ----------------
__device__ __forceinline__ float tf32r(float x)
{
    uint32_t u;
    asm("cvt.rna.tf32.f32 %0, %1;" : "=r"(u) : "f"(x));
    return __uint_as_float(u);
}

__device__ __forceinline__ void mma_tf32(float* c, const uint32_t* a, const uint32_t* b)
{
    asm volatile("mma.sync.aligned.m16n8k8.row.col.f32.tf32.tf32.f32 "
                 "{%0,%1,%2,%3}, {%4,%5,%6,%7}, {%8,%9}, {%0,%1,%2,%3};"
                 : "+f"(c[0]), "+f"(c[1]), "+f"(c[2]), "+f"(c[3])
                 : "r"(a[0]), "r"(a[1]), "r"(a[2]), "r"(a[3]), "r"(b[0]), "r"(b[1]));
}

__device__ __forceinline__ void gemm_core(const float* __restrict__ W,
                                          const float* __restrict__ X,
                                          float* __restrict__ Y,
                                          const float* __restrict__ bias,
                                          int I, int nb,
                                          float (*Ws)[20], float (*Xs)[65])
{
    int tid = threadIdx.x;
    int warp = tid >> 5, lane = tid & 31;
    int g = lane >> 2, j = lane & 3;
    int warp_o = warp & 3, warp_n = warp >> 2;

    float acc[2][4][4];
#pragma unroll
    for (int mo = 0; mo < 2; mo++)
#pragma unroll
        for (int nn = 0; nn < 4; nn++)
#pragma unroll
            for (int r = 0; r < 4; r++) acc[mo][nn][r] = 0.f;

    int wrow = tid >> 1, whf = (tid & 1) * 8;
    int xrow = tid >> 4, xc4 = (tid & 15) * 4;

    for (int kt = 0; kt < I; kt += 16) {
        float4 w0 = *(const float4*)&W[(long)wrow * I + kt + whf];
        float4 w1 = *(const float4*)&W[(long)wrow * I + kt + whf + 4];
        Ws[wrow][whf + 0] = tf32r(w0.x); Ws[wrow][whf + 1] = tf32r(w0.y);
        Ws[wrow][whf + 2] = tf32r(w0.z); Ws[wrow][whf + 3] = tf32r(w0.w);
        Ws[wrow][whf + 4] = tf32r(w1.x); Ws[wrow][whf + 5] = tf32r(w1.y);
        Ws[wrow][whf + 6] = tf32r(w1.z); Ws[wrow][whf + 7] = tf32r(w1.w);
        float4 xv = *(const float4*)&X[(long)(kt + xrow) * NP + nb + xc4];
        Xs[xrow][xc4 + 0] = tf32r(xv.x); Xs[xrow][xc4 + 1] = tf32r(xv.y);
        Xs[xrow][xc4 + 2] = tf32r(xv.z); Xs[xrow][xc4 + 3] = tf32r(xv.w);
        __syncthreads();
#pragma unroll
        for (int kk = 0; kk < 16; kk += 8) {
            uint32_t a[2][4], b[4][2];
#pragma unroll
            for (int mo = 0; mo < 2; mo++) {
                int r0 = warp_o * 32 + mo * 16 + g;
                a[mo][0] = __float_as_uint(Ws[r0][kk + j]);
                a[mo][1] = __float_as_uint(Ws[r0 + 8][kk + j]);
                a[mo][2] = __float_as_uint(Ws[r0][kk + j + 4]);
                a[mo][3] = __float_as_uint(Ws[r0 + 8][kk + j + 4]);
            }
#pragma unroll
            for (int nn = 0; nn < 4; nn++) {
                int cc = warp_n * 32 + nn * 8 + g;
                b[nn][0] = __float_as_uint(Xs[kk + j][cc]);
                b[nn][1] = __float_as_uint(Xs[kk + j + 4][cc]);
            }
#pragma unroll
            for (int mo = 0; mo < 2; mo++)
#pragma unroll
                for (int nn = 0; nn < 4; nn++)
                    mma_tf32(acc[mo][nn], a[mo], b[nn]);
        }
        __syncthreads();
    }

#pragma unroll
    for (int mo = 0; mo < 2; mo++) {
        int r0 = warp_o * 32 + mo * 16 + g;
        float bs0 = bias ? bias[r0] : 0.f;
        float bs1 = bias ? bias[r0 + 8] : 0.f;
#pragma unroll
        for (int nn = 0; nn < 4; nn++) {
            int col = nb + warp_n * 32 + nn * 8 + j * 2;
            float2 v0 = make_float2(acc[mo][nn][0] + bs0, acc[mo][nn][1] + bs0);
            float2 v1 = make_float2(acc[mo][nn][2] + bs1, acc[mo][nn][3] + bs1);
            *(float2*)&Y[(long)r0 * NP + col] = v0;
            *(float2*)&Y[(long)(r0 + 8) * NP + col] = v1;
        }
    }
}

__global__ void gemm_dualW_k(const float* __restrict__ W1, const float* __restrict__ W2,
                             int osplit, const float* __restrict__ X, long xB,
                             float* __restrict__ Y1, float* __restrict__ Y2, long yB, int I)
{
    __shared__ float Ws[128][20];
    __shared__ float Xs[16][65];
    int ob = blockIdx.y * 128, b = blockIdx.z;
    const float* W; float* Y;
    if (ob < osplit) { W = W1 + (long)ob * I;            Y = Y1 + (long)b * yB + (long)ob * NP; }
    else             { W = W2 + (long)(ob - osplit) * I; Y = Y2 + (long)b * yB + (long)(ob - osplit) * NP; }
    gemm_core(W, X + (long)b * xB, Y, nullptr, I, blockIdx.x * 64, Ws, Xs);
}

__global__ void gemm_dualX_k(const float* __restrict__ W1, const float* __restrict__ W2,
                             const float* __restrict__ X1, const float* __restrict__ X2, long xB,
                             float* __restrict__ Y1, float* __restrict__ Y2, long yB,
                             const float* __restrict__ b1, const float* __restrict__ b2, int I)
{
    __shared__ float Ws[128][20];
    __shared__ float Xs[16][65];
    int z = blockIdx.z, b = z & 1, sel = z >> 1;
    int ob = blockIdx.y * 128;
    const float* W = (sel ? W2 : W1) + (long)ob * I;
    const float* X = (sel ? X2 : X1) + (long)b * xB;
    float*       Y = (sel ? Y2 : Y1) + (long)b * yB + (long)ob * NP;
    const float* bs = sel ? b2 : b1;
    gemm_core(W, X, Y, bs ? bs + ob : nullptr, I, blockIdx.x * 64, Ws, Xs);
}

__global__ void gemm_tf32_k(const float* __restrict__ W, const float* __restrict__ X,
                            float* __restrict__ Y, const float* __restrict__ bias,
                            int I, long xB, long yB)
{
    __shared__ float Ws[128][20];
    __shared__ float Xs[16][65];
    int ob = blockIdx.y * 128, b = blockIdx.z;
    gemm_core(W + (long)ob * I, X + (long)b * xB, Y + (long)b * yB + (long)ob * NP,
              bias ? bias + ob : nullptr, I, blockIdx.x * 64, Ws, Xs);
}

// ---------------- fused DFT: smem tables copied from global ----------------
__device__ __forceinline__ void copy_tables(float2* T1, float2* T2, float2* T3, int tid)
{
    const float4* s1 = (const float4*)gT1; float4* d1 = (float4*)T1;
    for (int i = tid; i < HT / 2; i += 256) d1[i] = s1[i];
    const float4* s2 = (const float4*)gT2; float4* d2 = (float4*)T2;
    for (int i = tid; i < NP / 2; i += 256) d2[i] = s2[i];
    const float4* s3 = (const float4*)gT3; float4* d3 = (float4*)T3;
    for (int i = tid; i < T3N / 2; i += 256) d3[i] = s3[i];
}

__device__ __forceinline__ void r2cw_stage(const float* img, const float2* T1,
                                           float2* out, int tid)
{
    for (int o = tid; o < HT; o += 256) {
        int r = o >> 5, k = o & 31;
        if (k >= 29) continue;
        const float* xr = img + r * 56;
        float ac0 = 0.f, as0 = 0.f, ac1 = 0.f, as1 = 0.f;
#pragma unroll
        for (int n = 0; n < 56; n += 2) {
            float2 w0 = T1[n * 32 + k];       float v0 = xr[n];
            ac0 = fmaf(v0, w0.x, ac0); as0 = fmaf(v0, w0.y, as0);
            float2 w1 = T1[(n + 1) * 32 + k]; float v1 = xr[n + 1];
            ac1 = fmaf(v1, w1.x, ac1); as1 = fmaf(v1, w1.y, as1);
        }
        out[o] = make_float2(ac0 + ac1, -(as0 + as1));
    }
}

// forward H-DFT core: returns (pr, pi) for output o
template<int SG>
__device__ __forceinline__ void c2ch_core(const float2* in, const float2* T2,
                                          int kh, int kx, float& pr, float& pi)
{
    float pr0 = 0.f, pi0 = 0.f, pr1 = 0.f, pi1 = 0.f;
#pragma unroll
    for (int r = 0; r < 56; r += 2) {
        float2 w0 = T2[r * 56 + kh];       float2 v0 = in[r * 32 + kx];
        float2 w1 = T2[(r + 1) * 56 + kh]; float2 v1 = in[(r + 1) * 32 + kx];
        if (SG > 0) {
            pr0 = fmaf(v0.x, w0.x, fmaf(v0.y, w0.y, pr0));
            pi0 = fmaf(v0.y, w0.x, fmaf(-v0.x, w0.y, pi0));
            pr1 = fmaf(v1.x, w1.x, fmaf(v1.y, w1.y, pr1));
            pi1 = fmaf(v1.y, w1.x, fmaf(-v1.x, w1.y, pi1));
        } else {
            pr0 = fmaf(v0.x, w0.x, fmaf(-v0.y, w0.y, pr0));
            pi0 = fmaf(v0.y, w0.x, fmaf(v0.x, w0.y, pi0));
            pr1 = fmaf(v1.x, w1.x, fmaf(-v1.y, w1.y, pr1));
            pi1 = fmaf(v1.y, w1.x, fmaf(v1.x, w1.y, pi1));
        }
    }
    pr = pr0 + pr1;
    pi = pi0 + pi1;
}

template<int SG>
__device__ __forceinline__ void c2ch_stage(const float2* in, const float2* T2,
                                           float2* out, int tid)
{
    for (int o = tid; o < HT; o += 256) {
        int kh = o >> 5, kx = o & 31;
        if (kx >= 29) continue;
        float pr, pi;
        c2ch_core<SG>(in, T2, kh, kx, pr, pi);
        out[o] = make_float2(pr, pi);
    }
}

// forward H-DFT fused with in-place complex product: io[o] = dft(in)[o] * io[o]
__device__ __forceinline__ void c2ch_mul_stage(const float2* in, const float2* T2,
                                               float2* io, int tid)
{
    for (int o = tid; o < HT; o += 256) {
        int kh = o >> 5, kx = o & 31;
        if (kx >= 29) continue;
        float pr, pi;
        c2ch_core<1>(in, T2, kh, kx, pr, pi);
        float2 c = io[o];
        io[o] = make_float2(pr * c.x - pi * c.y, pr * c.y + pi * c.x);
    }
}

// forward H-DFT fused with complex-weight multiply from global cw
__device__ __forceinline__ void c2ch_cw_stage(const float2* in, const float2* T2,
                                              const float* __restrict__ cw, int c,
                                              float2* out, int tid)
{
    for (int o = tid; o < HT; o += 256) {
        int kh = o >> 5, kx = o & 31;
        if (kx >= 29) continue;
        float pr, pi;
        c2ch_core<1>(in, T2, kh, kx, pr, pi);
        long wb = (((long)c * 56 + kh) * 29 + kx) * 2;
        float wr = cw[wb], wi = cw[wb + 1];
        out[o] = make_float2(pr * wr - pi * wi, pr * wi + pi * wr);
    }
}

// ---------------- fused spectral branch ----------------
extern "C" __global__ void spec_fused_k(const float* __restrict__ sq,
                                        const float* __restrict__ skv,
                                        const float* __restrict__ dww,
                                        const float* __restrict__ dwb,
                                        float* __restrict__ out)
{
    extern __shared__ float sm[];
    float*  img = sm;                      // 3136
    float2* A   = (float2*)(sm + NP);      // 1792
    float2* Cf  = A + HT;                  // 1792
    float2* T1  = Cf + HT;
    float2* T2  = T1 + HT;
    float2* T3  = T2 + NP;
    int tid = threadIdx.x;
    int c = blockIdx.x, b = blockIdx.y;

    copy_tables(T1, T2, T3, tid);
    const float* qp = sq  + ((long)b * 256 + c) * NP;
    const float* kp = skv + ((long)b * 512 + c) * NP;
    const float* vp = skv + ((long)b * 512 + 256 + c) * NP;

    for (int i = tid; i < NP; i += 256) img[i] = qp[i];
    __syncthreads();
    r2cw_stage(img, T1, A, tid);
    __syncthreads();
    c2ch_stage<1>(A, T2, Cf, tid);         // Cf = Fq
    for (int i = tid; i < NP; i += 256) img[i] = kp[i];
    __syncthreads();
    r2cw_stage(img, T1, A, tid);
    __syncthreads();
    c2ch_mul_stage(A, T2, Cf, tid);        // Cf = Fk * Fq  (in place)
    __syncthreads();
    c2ch_stage<-1>(Cf, T2, A, tid);        // A = inverse along H
    for (int i = tid; i < NP; i += 256) img[i] = vp[i];
    __syncthreads();

    float wr[9];
#pragma unroll
    for (int i = 0; i < 9; i++) wr[i] = dww[c * 9 + i];
    float bsv = dwb[c];
    long ob = ((long)b * 256 + c) * NP;
    const float sc = 1.0f / 175616.0f;
    for (int o = tid; o < NP; o += 256) {
        int y = o / 56, x = o % 56;
        float a0 = 0.f, a1 = 0.f;
#pragma unroll
        for (int k = 0; k < 28; k += 2) {
            float2 w0 = T3[k * 56 + x];       float2 v0 = A[y * 32 + k];
            a0 = fmaf(v0.x, w0.x, fmaf(v0.y, w0.y, a0));
            float2 w1 = T3[(k + 1) * 56 + x]; float2 v1 = A[y * 32 + k + 1];
            a1 = fmaf(v1.x, w1.x, fmaf(v1.y, w1.y, a1));
        }
        {
            float2 w = T3[28 * 56 + x]; float2 v = A[y * 32 + 28];
            a0 = fmaf(v.x, w.x, fmaf(v.y, w.y, a0));
        }
        float acc = a0 + a1;
        float dv = bsv;
#pragma unroll
        for (int dy = -1; dy <= 1; dy++) {
            int yy = y + dy;
            if ((unsigned)yy >= 56u) continue;
#pragma unroll
            for (int dx = -1; dx <= 1; dx++) {
                int xx = x + dx;
                if ((unsigned)xx >= 56u) continue;
                dv += wr[(dy + 1) * 3 + dx + 1] * img[yy * 56 + xx];
            }
        }
        out[ob + o] = (sc * acc) * img[o] + dv;
    }
}

// ---------------- fused token spectral-residual ----------------
extern "C" __global__ void token_fused_k(const float* __restrict__ tkv,
                                         const float* __restrict__ cw,
                                         float* __restrict__ xat)
{
    extern __shared__ float sm[];
    float*  img = sm;
    float2* A   = (float2*)(sm + NP);
    float2* Bf  = A + HT;
    float2* T1  = Bf + HT;
    float2* T2  = T1 + HT;
    float2* T3  = T2 + NP;
    int tid = threadIdx.x;
    int c = blockIdx.x, b = blockIdx.y;

    copy_tables(T1, T2, T3, tid);
    const float* vp = tkv + (long)b * C2N + CN + (long)c * NP;
    for (int i = tid; i < NP; i += 256) img[i] = vp[i];
    __syncthreads();
    r2cw_stage(img, T1, A, tid);
    __syncthreads();
    c2ch_cw_stage(A, T2, cw, c, Bf, tid);  // Bf = Fv * W
    __syncthreads();
    c2ch_stage<-1>(Bf, T2, A, tid);
    __syncthreads();
    long ob = ((long)b * 256 + c) * NP;
    const float sc = 1.0f / 3136.0f;
    for (int o = tid; o < NP; o += 256) {
        int y = o / 56, x = o % 56;
        float a0 = 0.f, a1 = 0.f;
#pragma unroll
        for (int k = 0; k < 28; k += 2) {
            float2 w0 = T3[k * 56 + x];       float2 v0 = A[y * 32 + k];
            a0 = fmaf(v0.x, w0.x, fmaf(v0.y, w0.y, a0));
            float2 w1 = T3[(k + 1) * 56 + x]; float2 v1 = A[y * 32 + k + 1];
            a1 = fmaf(v1.x, w1.x, fmaf(v1.y, w1.y, a1));
        }
        {
            float2 w = T3[28 * 56 + x]; float2 v = A[y * 32 + 28];
            a0 = fmaf(v.x, w.x, fmaf(v.y, w.y, a0));
        }
        xat[ob + o] += sc * (a0 + a1);
    }
}

// ---------------- bf16 conversions ----------------
__global__ void cvtqk2_k(const float* __restrict__ tq, const float* __restrict__ tkv,
                         __nv_bfloat162* __restrict__ qb, __nv_bfloat162* __restrict__ kb,
                         float scale)
{
    const long HALF = (long)Bb * 8 * NP * 16;
    long i = (long)blockIdx.x * blockDim.x + threadIdx.x;
    if (i >= 2 * HALF) return;
    int isK = i >= HALF;
    long ii = isK ? i - HALF : i;
    int p = (int)(ii & 15);
    long t = ii >> 4;
    int n = (int)(t % NP);
    long t2 = t / NP;
    int h = (int)(t2 & 7), b = (int)(t2 >> 3);
    if (isK) {
        long s0 = (long)b * C2N + (long)(h * 32 + 2 * p) * NP + n;
        kb[ii] = __floats2bfloat162_rn(tkv[s0], tkv[s0 + NP]);
    } else {
        long s0 = (long)b * CN + (long)(h * 32 + 2 * p) * NP + n;
        qb[ii] = __floats2bfloat162_rn(tq[s0] * scale, tq[s0 + NP] * scale);
    }
}

__global__ void cvtv_k(const float* __restrict__ tkv, __nv_bfloat162* __restrict__ dst)
{
    long i = (long)blockIdx.x * blockDim.x + threadIdx.x;
    if (i >= (long)Bb * 256 * NPH) return;
    int n2 = (int)(i % NPH);
    long cr = i / NPH;
    int b = (int)(cr >> 8), c = (int)(cr & 255);
    long s = (long)b * C2N + CN + (long)c * NP + 2 * n2;
    dst[i] = __floats2bfloat162_rn(tkv[s], tkv[s + 1]);
}

// ---------------- split-K flash attention ----------------
__device__ __forceinline__ void mma16816(float* c, const uint32_t* a, const uint32_t* b)
{
    asm volatile("mma.sync.aligned.m16n8k16.row.col.f32.bf16.bf16.f32 "
                 "{%0,%1,%2,%3}, {%4,%5,%6,%7}, {%8,%9}, {%0,%1,%2,%3};"
                 : "+f"(c[0]), "+f"(c[1]), "+f"(c[2]), "+f"(c[3])
                 : "r"(a[0]), "r"(a[1]), "r"(a[2]), "r"(a[3]), "r"(b[0]), "r"(b[1]));
}

__device__ __forceinline__ uint32_t packbf(float lo, float hi)
{
    __nv_bfloat162 h = __floats2bfloat162_rn(lo, hi);
    return *(uint32_t*)&h;
}

__global__ void flash_mma_k(const __nv_bfloat162* __restrict__ Qb,
                            const __nv_bfloat162* __restrict__ Kb,
                            const __nv_bfloat162* __restrict__ Vb,
                            float* __restrict__ Osp, float* __restrict__ Mv,
                            float* __restrict__ Lv)
{
    __shared__ uint32_t Ks[32 * 16];
    __shared__ uint32_t Vs[32 * 16];
    int z = blockIdx.z, b = z & 1, split = z >> 1;
    int h = blockIdx.y;
    int tid = threadIdx.x;
    int warp = tid >> 5, lane = tid & 31;
    int g = lane >> 2, j = lane & 3;
    int q0 = blockIdx.x * 128 + warp * 16;
    bool act = q0 < NP;
    int q0c = act ? q0 : NP - 16;
    const uint32_t* Qh = (const uint32_t*)(Qb + (long)(b * 8 + h) * NP * 16);
    const uint32_t* Kh = (const uint32_t*)(Kb + (long)(b * 8 + h) * NP * 16);
    const uint32_t* Vh = (const uint32_t*)(Vb + (long)(b * 256 + h * 32) * NPH);

    uint32_t qa[2][4];
#pragma unroll
    for (int kc = 0; kc < 2; kc++) {
        qa[kc][0] = Qh[(q0c + g)     * 16 + kc * 8 + j];
        qa[kc][1] = Qh[(q0c + g + 8) * 16 + kc * 8 + j];
        qa[kc][2] = Qh[(q0c + g)     * 16 + kc * 8 + j + 4];
        qa[kc][3] = Qh[(q0c + g + 8) * 16 + kc * 8 + j + 4];
    }

    float o_[4][4];
#pragma unroll
    for (int d = 0; d < 4; d++)
#pragma unroll
        for (int r = 0; r < 4; r++) o_[d][r] = 0.f;
    float mlo = -1e30f, mhi = -1e30f, llo = 0.f, lhi = 0.f;

    int kt0 = split * 49;
#pragma unroll 1
    for (int kt = kt0; kt < kt0 + 49; kt++) {
        int kb = kt * 32;
        __syncthreads();
        {
            int t0 = tid, t1 = tid + 256;
            Ks[t0] = Kh[kb * 16 + t0];
            Ks[t1] = Kh[kb * 16 + t1];
            Vs[t0] = Vh[(long)(t0 >> 4) * NPH + (kb >> 1) + (t0 & 15)];
            Vs[t1] = Vh[(long)(t1 >> 4) * NPH + (kb >> 1) + (t1 & 15)];
        }
        __syncthreads();

        float s[2][2][4];
#pragma unroll
        for (int sub = 0; sub < 2; sub++) {
#pragma unroll
            for (int nc = 0; nc < 2; nc++) {
                uint32_t kf[2][2];
#pragma unroll
                for (int kc = 0; kc < 2; kc++) {
                    int keyl = sub * 16 + nc * 8 + g;
                    kf[kc][0] = Ks[keyl * 16 + kc * 8 + j];
                    kf[kc][1] = Ks[keyl * 16 + kc * 8 + j + 4];
                }
                s[sub][nc][0] = 0.f; s[sub][nc][1] = 0.f;
                s[sub][nc][2] = 0.f; s[sub][nc][3] = 0.f;
                mma16816(s[sub][nc], qa[0], kf[0]);
                mma16816(s[sub][nc], qa[1], kf[1]);
            }
        }

        float tlo = -1e30f, thi = -1e30f;
#pragma unroll
        for (int sub = 0; sub < 2; sub++)
#pragma unroll
            for (int nc = 0; nc < 2; nc++) {
                tlo = fmaxf(tlo, fmaxf(s[sub][nc][0], s[sub][nc][1]));
                thi = fmaxf(thi, fmaxf(s[sub][nc][2], s[sub][nc][3]));
            }
        tlo = fmaxf(tlo, __shfl_xor_sync(0xffffffff, tlo, 1));
        tlo = fmaxf(tlo, __shfl_xor_sync(0xffffffff, tlo, 2));
        thi = fmaxf(thi, __shfl_xor_sync(0xffffffff, thi, 1));
        thi = fmaxf(thi, __shfl_xor_sync(0xffffffff, thi, 2));
        float mnlo = fmaxf(mlo, tlo), mnhi = fmaxf(mhi, thi);
        float clo = __expf(mlo - mnlo), chi = __expf(mhi - mnhi);

        uint32_t pa[2][4];
        float sumlo = 0.f, sumhi = 0.f;
#pragma unroll
        for (int sub = 0; sub < 2; sub++) {
#pragma unroll
            for (int nc = 0; nc < 2; nc++) {
                float p0 = __expf(s[sub][nc][0] - mnlo);
                float p1 = __expf(s[sub][nc][1] - mnlo);
                float p2 = __expf(s[sub][nc][2] - mnhi);
                float p3 = __expf(s[sub][nc][3] - mnhi);
                sumlo += p0 + p1; sumhi += p2 + p3;
                pa[sub][nc * 2 + 0] = packbf(p0, p1);
                pa[sub][nc * 2 + 1] = packbf(p2, p3);
            }
        }
        sumlo += __shfl_xor_sync(0xffffffff, sumlo, 1);
        sumlo += __shfl_xor_sync(0xffffffff, sumlo, 2);
        sumhi += __shfl_xor_sync(0xffffffff, sumhi, 1);
        sumhi += __shfl_xor_sync(0xffffffff, sumhi, 2);
        llo = llo * clo + sumlo;
        lhi = lhi * chi + sumhi;
#pragma unroll
        for (int d = 0; d < 4; d++) {
            o_[d][0] *= clo; o_[d][1] *= clo;
            o_[d][2] *= chi; o_[d][3] *= chi;
        }
        mlo = mnlo; mhi = mnhi;

#pragma unroll
        for (int dc = 0; dc < 4; dc++) {
#pragma unroll
            for (int sub = 0; sub < 2; sub++) {
                uint32_t vf[2];
                int vrow = (dc * 8 + g) * 16 + sub * 8;
                vf[0] = Vs[vrow + j];
                vf[1] = Vs[vrow + j + 4];
                mma16816(o_[dc], pa[sub], vf);
            }
        }
    }

    if (act) {
        float* Ob = Osp + (long)split * TOT;
#pragma unroll
        for (int dc = 0; dc < 4; dc++) {
            long d0 = (long)(b * 256 + h * 32 + dc * 8 + 2 * j) * NP;
            Ob[d0 + q0 + g]          = o_[dc][0];
            Ob[d0 + NP + q0 + g]     = o_[dc][1];
            Ob[d0 + q0 + g + 8]      = o_[dc][2];
            Ob[d0 + NP + q0 + g + 8] = o_[dc][3];
        }
        if (j == 0) {
            long mb = ((long)split * 16 + b * 8 + h) * NP;
            Mv[mb + q0 + g] = mlo;     Lv[mb + q0 + g] = llo;
            Mv[mb + q0 + g + 8] = mhi; Lv[mb + q0 + g + 8] = lhi;
        }
    }
}

__global__ void combine_k(const float* __restrict__ Osp, const float* __restrict__ Mv,
                          const float* __restrict__ Lv, float* __restrict__ xat)
{
    long i = (long)blockIdx.x * blockDim.x + threadIdx.x;
    if (i >= TOT) return;
    int row = (int)(i / NP);
    int n = (int)(i % NP);
    int bh = row >> 5;
    long mb = (long)bh * NP + n;
    float m0 = Mv[mb], m1 = Mv[16L * NP + mb];
    float l0 = Lv[mb], l1 = Lv[16L * NP + mb];
    float m = fmaxf(m0, m1);
    float a0 = __expf(m0 - m), a1 = __expf(m1 - m);
    float o = Osp[i] * a0 + Osp[TOT + i] * a1;
    xat[i] = o / (l0 * a0 + l1 * a1);
}

// ---------------- fuse ----------------
__global__ void gate_k(const float* __restrict__ hraw, const float* __restrict__ gam,
                       const float* __restrict__ bet, const float* __restrict__ w2,
                       const float* __restrict__ b2p, float* __restrict__ gate)
{
    int b = blockIdx.y;
    int n = blockIdx.x * 128 + threadIdx.x;
    if (n >= NP) return;
    const float inv = rsqrtf(1.f + 1e-5f);
    const float* hb = hraw + (long)b * CN + n;
    float g = b2p[0];
#pragma unroll 8
    for (int c = 0; c < 256; c++) {
        float hv = hb[(long)c * NP] * inv * gam[c] + bet[c];
        g = fmaf(w2[c], fmaxf(hv, 0.f), g);
    }
    gate[(long)b * NP + n] = 1.f / (1.f + __expf(-g));
}

__global__ void blend_k(const float* __restrict__ fuse, const float* __restrict__ gate,
                        float* __restrict__ out)
{
    long i = (long)blockIdx.x * blockDim.x + threadIdx.x;
    if (i >= TOT) return;
    long b = i / CN;
    long n = i % NP;
    float g = gate[b * NP + n];
    long fidx = i + b * CN;
    out[i] = g * fuse[fidx] + (1.f - g) * fuse[fidx + CN];
}

extern "C" void kernel_launch(void* const* d_in, const int* in_sizes, int n_in,
                              void* d_out, int out_size)
{
    const float* x        = (const float*)d_in[0];
    const float* ctx      = (const float*)d_in[1];
    const float* s_q_w    = (const float*)d_in[2];
    const float* s_kv_w   = (const float*)d_in[3];
    const float* s_proj_w = (const float*)d_in[4];
    const float* s_proj_b = (const float*)d_in[5];
    const float* s_dw_w   = (const float*)d_in[6];
    const float* s_dw_b   = (const float*)d_in[7];
    const float* t_q_w    = (const float*)d_in[8];
    const float* t_kv_w   = (const float*)d_in[9];
    const float* t_proj_w = (const float*)d_in[10];
    const float* t_proj_b = (const float*)d_in[11];
    const float* t_cw     = (const float*)d_in[12];
    const float* g_w1     = (const float*)d_in[13];
    const float* g_bn_g   = (const float*)d_in[14];
    const float* g_bn_b   = (const float*)d_in[15];
    const float* g_w2     = (const float*)d_in[16];
    const float* g_b2     = (const float*)d_in[17];
    float* out = (float*)d_out;

    float *sq, *skv, *tq, *tkv, *spre, *xat, *fuse, *hbuf, *gate, *osp, *mv, *lv;
    __nv_bfloat162 *qb, *kb, *vb;
    cudaGetSymbolAddress((void**)&sq,   g_sq);
    cudaGetSymbolAddress((void**)&skv,  g_skv);
    cudaGetSymbolAddress((void**)&tq,   g_tq);
    cudaGetSymbolAddress((void**)&tkv,  g_tkv);
    cudaGetSymbolAddress((void**)&spre, g_spre);
    cudaGetSymbolAddress((void**)&xat,  g_xat);
    cudaGetSymbolAddress((void**)&fuse, g_fusb);
    cudaGetSymbolAddress((void**)&hbuf, g_hbuf);
    cudaGetSymbolAddress((void**)&gate, g_gate);
    cudaGetSymbolAddress((void**)&osp,  g_osp);
    cudaGetSymbolAddress((void**)&mv,   g_mv);
    cudaGetSymbolAddress((void**)&lv,   g_lv);
    cudaGetSymbolAddress((void**)&qb,   g_qb);
    cudaGetSymbolAddress((void**)&kb,   g_kb);
    cudaGetSymbolAddress((void**)&vb,   g_vb);

    // smem: img + (A,Cf/Bf) + tables (T1,T2,T3)
    const int FUSED_SMEM = (NP + 2 * (2 * HT + HT + NP + T3N)) * 4;   // ~91.4 KB
    cudaFuncSetAttribute(spec_fused_k,  cudaFuncAttributeMaxDynamicSharedMemorySize, FUSED_SMEM);
    cudaFuncSetAttribute(token_fused_k, cudaFuncAttributeMaxDynamicSharedMemorySize, FUSED_SMEM);

    const float SCALE = 0.17677669529663687f;
    dim3 blk256(256), blk128(128);
    dim3 gC(256, Bb);

    init_tables_k<<<1, 256>>>();

    gemm_dualW_k<<<dim3(49, 4, Bb), blk256>>>(s_q_w, t_q_w, 256, x, CN, sq, tq, CN, 256);
    gemm_dualW_k<<<dim3(49, 8, Bb), blk256>>>(s_kv_w, t_kv_w, 512, ctx, CN, skv, tkv, C2N, 256);

    spec_fused_k<<<gC, blk256, FUSED_SMEM>>>(sq, skv, s_dw_w, s_dw_b, spre);

    cvtqk2_k<<<dim3(6272), blk256>>>(tq, tkv, qb, kb, SCALE);
    cvtv_k<<<dim3(3136), blk256>>>(tkv, vb);
    flash_mma_k<<<dim3(25, 8, Bb * 2), blk256>>>(qb, kb, vb, osp, mv, lv);
    combine_k<<<dim3((unsigned)((TOT + 255) / 256)), blk256>>>(osp, mv, lv, xat);
    token_fused_k<<<gC, blk256, FUSED_SMEM>>>(tkv, t_cw, xat);

    gemm_dualX_k<<<dim3(49, 2, 4), blk256>>>(s_proj_w, t_proj_w, spre, xat, CN,
                                             fuse, fuse + CN, C2N,
                                             s_proj_b, t_proj_b, 256);

    gemm_tf32_k<<<dim3(49, 2, Bb), blk256>>>(g_w1, fuse, hbuf, nullptr, 512, C2N, CN);
    gate_k<<<dim3(25, Bb), blk128>>>(hbuf, g_bn_g, g_bn_b, g_w2, g_b2, gate);
    blend_k<<<dim3((unsigned)((TOT + 255) / 256)), blk256>>>(fuse, gate, out);
}